// round 4
// baseline (speedup 1.0000x reference)
#include <cuda_runtime.h>

#define D    768
#define NH   12
#define DKH  64
#define TT   16
#define ENCL 256
#define DFF  3072
#define NV   32128
#define NL   4
#define NB   2
#define EPSF 1e-6f
#define RSQRT_D 0.03608439182435161f   // 768^-0.5
#define NBLK 148
#define NTHR 256

// ------------------------------------------------------------------ scratch
__device__ float g_x  [NB*D];
__device__ float g_q  [NB*D];
__device__ float g_q2 [NB*D];
__device__ float g_att[NB*D];
__device__ float g_ff [NB*DFF];
__device__ float g_kc [NL*NB*TT*D];
__device__ float g_vc [NL*NB*TT*D];
__device__ float g_ckt[NL*NB*NH*DKH*ENCL];   // cross K transposed [l][b][h][dk][pos]
__device__ float g_cv [NL*NB*ENCL*D];        // cross V natural
__device__ unsigned long long g_amax[NB];
__device__ unsigned g_bar_count;
__device__ volatile unsigned g_bar_gen;

struct Params {
    const float *emb, *ln1, *qw, *kw, *vw, *ow, *ln2, *cqw, *cow, *ln3, *wi, *wo, *fln, *rb;
    float* out;
};

// ------------------------------------------------------------------ grid barrier
__device__ __forceinline__ void gsync() {
    __syncthreads();
    if (threadIdx.x == 0) {
        unsigned gen = g_bar_gen;
        __threadfence();
        if (atomicAdd(&g_bar_count, 1u) == NBLK - 1) {
            g_bar_count = 0;
            __threadfence();
            g_bar_gen = gen + 1;
        } else {
            while (g_bar_gen == gen) { }
            __threadfence();
        }
    }
    __syncthreads();
}

// ------------------------------------------------------------------ rms (redundant per block)
__device__ __forceinline__ float2 rms2(float* sred) {
    float s0 = 0.f, s1 = 0.f;
    for (int i = threadIdx.x; i < D; i += NTHR) {
        float a = __ldcg(&g_x[i]), b = __ldcg(&g_x[D + i]);
        s0 += a * a; s1 += b * b;
    }
    #pragma unroll
    for (int o = 16; o; o >>= 1) {
        s0 += __shfl_xor_sync(0xffffffffu, s0, o);
        s1 += __shfl_xor_sync(0xffffffffu, s1, o);
    }
    if ((threadIdx.x & 31) == 0) {
        sred[threadIdx.x >> 5]       = s0;
        sred[8 + (threadIdx.x >> 5)] = s1;
    }
    __syncthreads();
    if (threadIdx.x == 0) {
        float t0 = 0.f, t1 = 0.f;
        #pragma unroll
        for (int w = 0; w < 8; w++) { t0 += sred[w]; t1 += sred[8 + w]; }
        sred[16] = rsqrtf(t0 / (float)D + EPSF);
        sred[17] = rsqrtf(t1 / (float)D + EPSF);
    }
    __syncthreads();
    float2 r; r.x = sred[16]; r.y = sred[17];
    __syncthreads();
    return r;
}

__device__ __forceinline__ void gemv_ksplit(
    const float* __restrict__ W, int Dout,
    const float* sh0, const float* sh1, int i0, int klen,
    int tile, float* o0, float* o1)
{
    int col = (tile << 8) + threadIdx.x;
    const float* Wp = W + (size_t)i0 * Dout + col;
    float a0 = 0.f, a1 = 0.f;
    #pragma unroll 8
    for (int i = 0; i < klen; i++) {
        float w = Wp[(size_t)i * Dout];
        a0 += sh0[i] * w; a1 += sh1[i] * w;
    }
    atomicAdd(o0 + col, a0);
    atomicAdd(o1 + col, a1);
}

__device__ __forceinline__ void fill_norm(float* sh0, float* sh1,
    const float* lnw, int i0, int klen, float2 inv)
{
    if (threadIdx.x < klen) {
        int i = threadIdx.x;
        float w = lnw[i0 + i];
        sh0[i] = __ldcg(&g_x[i0 + i])     * inv.x * w;
        sh1[i] = __ldcg(&g_x[D + i0 + i]) * inv.y * w;
    }
    __syncthreads();
}

// ------------------------------------------------------------------ persistent decode kernel
__global__ __launch_bounds__(NTHR) void k_decode(Params p) {
    __shared__ float s[2048];
    float* sred = s;          // [18]
    float* sh0  = s + 32;     // [64]
    float* sh1  = s + 96;     // [64]
    const int bx = blockIdx.x, tid = threadIdx.x;

    // ---- init (re-run each graph replay for determinism)
    for (int i = bx * NTHR + tid; i < NL * NB * TT * D; i += NBLK * NTHR) {
        g_kc[i] = 0.f; g_vc[i] = 0.f;
    }
    for (int i = bx * NTHR + tid; i < NB * D; i += NBLK * NTHR) g_q[i] = 0.f;
    for (int i = bx * NTHR + tid; i < NB * DFF; i += NBLK * NTHR) g_ff[i] = 0.f;
    if (bx == 0 && tid < NB) g_amax[tid] = 0ull;
    gsync();

    for (int t = 0; t < TT; t++) {
        // ---- embed phase
        if (bx == 0) {
            __shared__ int stok[NB];
            if (tid < NB) {
                int tok = 0;
                if (t > 0) {
                    unsigned long long k = *((volatile unsigned long long*)&g_amax[tid]);
                    tok = NV - 1 - (int)(k & 0xffffffffull);
                }
                stok[tid] = tok;
            }
            __syncthreads();
            for (int i = tid; i < NB * D; i += NTHR) {
                int b = i / D, d = i % D;
                g_x[i] = p.emb[(size_t)stok[b] * D + d];
            }
        }
        gsync();

        for (int l = 0; l < NL; l++) {
            const size_t MO  = (size_t)l * D * D;
            const float* kcb = g_kc + ((size_t)(l * NB) * TT + t) * D;
            const float* vcb = g_vc + ((size_t)(l * NB) * TT + t) * D;

            // ---- phase: qkv gemv (144 jobs: 3 mats x 3 tiles x 16 splits, klen=48)
            if (bx < 144) {
                float2 inv = rms2(sred);
                int mat = bx / 48, r = bx % 48, tile = r / 16, ks = r % 16;
                int i0 = ks * 48;
                fill_norm(sh0, sh1, p.ln1 + l * D, i0, 48, inv);
                if (mat == 0)
                    gemv_ksplit(p.qw + MO, D, sh0, sh1, i0, 48, tile, g_q, g_q + D);
                else if (mat == 1)
                    gemv_ksplit(p.kw + MO, D, sh0, sh1, i0, 48, tile,
                                (float*)kcb, (float*)kcb + TT * D);
                else
                    gemv_ksplit(p.vw + MO, D, sh0, sh1, i0, 48, tile,
                                (float*)vcb, (float*)vcb + TT * D);
            } else if (bx == 147 && tid < NB) {
                g_amax[tid] = 0ull;   // reset for this step's logits argmax
            }
            gsync();

            // ---- phase: self-attn (24 jobs) + idle blocks zero g_q2, g_ff
            if (bx < 24) {
                int b = bx / NH, h = bx % NH;
                float* sq = s + 32; float* sp = s + 96; float* se = s + 112;
                if (tid < DKH) sq[tid] = __ldcg(&g_q[b * D + h * DKH + tid]);
                __syncthreads();
                int n = t + 1;
                if (tid < n) {
                    const float* kp = g_kc + ((size_t)(l * NB + b) * TT + tid) * D + h * DKH;
                    float sc = 0.f;
                    #pragma unroll
                    for (int d = 0; d < DKH; d++) sc += sq[d] * __ldcg(kp + d);
                    sp[tid] = sc + p.rb[(t - tid) * NH + h];
                }
                __syncthreads();
                if (tid < n) {
                    float mx = -1e30f;
                    for (int j = 0; j < n; j++) mx = fmaxf(mx, sp[j]);
                    se[tid] = expf(sp[tid] - mx);
                }
                __syncthreads();
                if (tid < DKH) {
                    float sum = 0.f, o = 0.f;
                    for (int j = 0; j < n; j++) {
                        sum += se[j];
                        o += se[j] * __ldcg(&g_vc[((size_t)(l * NB + b) * TT + j) * D + h * DKH + tid]);
                    }
                    g_att[b * D + h * DKH + tid] = o / sum;
                }
            } else {
                int idx = (bx - 24) * NTHR + tid;
                if (idx < NB * D) g_q2[idx] = 0.f;
                else if (idx < NB * D + NB * DFF) g_ff[idx - NB * D] = 0.f;
            }
            gsync();

            // ---- phase: o-proj + residual (144 jobs: 3 tiles x 48 splits, klen=16)
            if (bx < 144) {
                int tile = bx / 48, ks = bx % 48, i0 = ks * 16;
                if (tid < 16) {
                    sh0[tid] = __ldcg(&g_att[i0 + tid]);
                    sh1[tid] = __ldcg(&g_att[D + i0 + tid]);
                }
                __syncthreads();
                gemv_ksplit(p.ow + MO, D, sh0, sh1, i0, 16, tile, g_x, g_x + D);
            }
            gsync();

            // ---- phase: cq gemv (144 jobs, klen=16) into g_q2
            if (bx < 144) {
                float2 inv = rms2(sred);
                int tile = bx / 48, ks = bx % 48, i0 = ks * 16;
                fill_norm(sh0, sh1, p.ln2 + l * D, i0, 16, inv);
                gemv_ksplit(p.cqw + MO, D, sh0, sh1, i0, 16, tile, g_q2, g_q2 + D);
            }
            gsync();

            // ---- phase: cross-attn (24 jobs) + idle blocks zero g_q
            if (bx < 24) {
                int b = bx / NH, h = bx % NH;
                float* sq  = s + 32;   // 64
                float* se  = s + 96;   // 256
                float* red = s + 352;  // 8
                float* sMS = s + 360;  // 2
                float* so  = s + 368;  // 4*64
                if (tid < DKH) sq[tid] = __ldcg(&g_q2[b * D + h * DKH + tid]);
                __syncthreads();
                const float* kt = g_ckt + ((size_t)((l * NB + b) * NH + h) * DKH) * ENCL;
                float sc = 0.f;
                #pragma unroll 16
                for (int d = 0; d < DKH; d++) sc += sq[d] * kt[(size_t)d * ENCL + tid];
                float m = sc;
                for (int o = 16; o; o >>= 1) m = fmaxf(m, __shfl_xor_sync(0xffffffffu, m, o));
                if ((tid & 31) == 0) red[tid >> 5] = m;
                __syncthreads();
                if (tid == 0) {
                    float mm = red[0];
                    for (int w = 1; w < 8; w++) mm = fmaxf(mm, red[w]);
                    sMS[0] = mm;
                }
                __syncthreads();
                float e = expf(sc - sMS[0]);
                se[tid] = e;
                float ss = e;
                for (int o = 16; o; o >>= 1) ss += __shfl_xor_sync(0xffffffffu, ss, o);
                if ((tid & 31) == 0) red[tid >> 5] = ss;
                __syncthreads();
                if (tid == 0) {
                    float t2 = 0.f;
                    for (int w = 0; w < 8; w++) t2 += red[w];
                    sMS[1] = t2;
                }
                __syncthreads();
                int g = tid >> 6, d = tid & 63;
                const float* vp = g_cv + (size_t)((l * NB + b) * ENCL) * D + h * DKH + d;
                float acc = 0.f;
                for (int j = g * 64; j < g * 64 + 64; j++) acc += se[j] * vp[(size_t)j * D];
                so[g * 64 + d] = acc;
                __syncthreads();
                if (tid < DKH)
                    g_att[b * D + h * DKH + tid] =
                        (so[tid] + so[64 + tid] + so[128 + tid] + so[192 + tid]) / sMS[1];
            } else {
                int idx = (bx - 24) * NTHR + tid;
                if (idx < NB * D) g_q[idx] = 0.f;
            }
            gsync();

            // ---- phase: co-proj + residual
            if (bx < 144) {
                int tile = bx / 48, ks = bx % 48, i0 = ks * 16;
                if (tid < 16) {
                    sh0[tid] = __ldcg(&g_att[i0 + tid]);
                    sh1[tid] = __ldcg(&g_att[D + i0 + tid]);
                }
                __syncthreads();
                gemv_ksplit(p.cow + MO, D, sh0, sh1, i0, 16, tile, g_x, g_x + D);
            }
            gsync();

            // ---- phase: wi gemv (144 jobs: 12 tiles x 12 splits, klen=64)
            if (bx < 144) {
                float2 inv = rms2(sred);
                int tile = bx / 12, ks = bx % 12, i0 = ks * 64;
                fill_norm(sh0, sh1, p.ln3 + l * D, i0, 64, inv);
                gemv_ksplit(p.wi + (size_t)l * D * DFF, DFF, sh0, sh1, i0, 64, tile,
                            g_ff, g_ff + DFF);
            }
            gsync();

            // ---- phase: wo gemv + residual (144 jobs: 3 tiles x 48 splits, klen=64)
            if (bx < 144) {
                int tile = bx / 48, ks = bx % 48, i0 = ks * 64;
                if (tid < 64) {
                    sh0[tid] = fmaxf(__ldcg(&g_ff[i0 + tid]), 0.f);
                    sh1[tid] = fmaxf(__ldcg(&g_ff[DFF + i0 + tid]), 0.f);
                }
                __syncthreads();
                gemv_ksplit(p.wo + (size_t)l * DFF * D, D, sh0, sh1, i0, 64, tile,
                            g_x, g_x + D);
            }
            gsync();
        }

        // ---- phase: final rms + logits + fused argmax (all 148 blocks)
        {
            float2 inv = rms2(sred);
            float* sx0 = s + 32;    // 768
            float* sx1 = s + 800;   // 768
            for (int i = tid; i < D; i += NTHR) {
                float w = p.fln[i] * RSQRT_D;
                sx0[i] = __ldcg(&g_x[i])     * inv.x * w;
                sx1[i] = __ldcg(&g_x[D + i]) * inv.y * w;
            }
            __syncthreads();
            int warp = tid >> 5, lane = tid & 31;
            unsigned long long best0 = 0ull, best1 = 0ull;
            for (int v = bx * 8 + warp; v < NV; v += NBLK * 8) {
                const float4* e = (const float4*)(p.emb + (size_t)v * D);
                float a0 = 0.f, a1 = 0.f;
                #pragma unroll
                for (int i = lane; i < D / 4; i += 32) {
                    float4 w = e[i];
                    a0 += w.x * sx0[4*i] + w.y * sx0[4*i+1] + w.z * sx0[4*i+2] + w.w * sx0[4*i+3];
                    a1 += w.x * sx1[4*i] + w.y * sx1[4*i+1] + w.z * sx1[4*i+2] + w.w * sx1[4*i+3];
                }
                for (int o = 16; o; o >>= 1) {
                    a0 += __shfl_xor_sync(0xffffffffu, a0, o);
                    a1 += __shfl_xor_sync(0xffffffffu, a1, o);
                }
                if (lane == 0) {
                    p.out[((size_t)0 * TT + t) * NV + v] = a0;
                    p.out[((size_t)1 * TT + t) * NV + v] = a1;
                    unsigned b0 = __float_as_uint(a0);
                    unsigned b1 = __float_as_uint(a1);
                    unsigned u0 = (b0 & 0x80000000u) ? ~b0 : (b0 | 0x80000000u);
                    unsigned u1 = (b1 & 0x80000000u) ? ~b1 : (b1 | 0x80000000u);
                    unsigned long long k0 = ((unsigned long long)u0 << 32) | (unsigned)(NV - 1 - v);
                    unsigned long long k1 = ((unsigned long long)u1 << 32) | (unsigned)(NV - 1 - v);
                    if (k0 > best0) best0 = k0;
                    if (k1 > best1) best1 = k1;
                }
            }
            if (lane == 0) {
                atomicMax(&g_amax[0], best0);
                atomicMax(&g_amax[1], best1);
            }
        }
        gsync();
    }
}

// ------------------------------------------------------------------ cross K/V precompute
__global__ __launch_bounds__(256) void k_cross_kv(
    const float* __restrict__ enc, const float* __restrict__ ckw,
    const float* __restrict__ cvw)
{
    __shared__ float sx[8][D];
    int bx = blockIdx.x;
    int c   = bx % 3; bx /= 3;
    int rb  = bx % 64; bx /= 64;
    int mat = bx % 2;
    int l   = bx / 2;
    int row0 = rb * 8;
    for (int i = threadIdx.x; i < 8 * D; i += 256)
        sx[i / D][i % D] = enc[(size_t)row0 * D + i];
    __syncthreads();
    const float* W = (mat == 0 ? ckw : cvw) + (size_t)l * D * D;
    int col = c * 256 + threadIdx.x;
    float acc[8];
    #pragma unroll
    for (int r = 0; r < 8; r++) acc[r] = 0.f;
    const float* Wp = W + col;
    #pragma unroll 4
    for (int i = 0; i < D; i++) {
        float w = Wp[(size_t)i * D];
        #pragma unroll
        for (int r = 0; r < 8; r++) acc[r] += sx[r][i] * w;
    }
    int h = col / DKH, dd = col % DKH;
    for (int r = 0; r < 8; r++) {
        int g = row0 + r; int b = g / ENCL; int pnum = g % ENCL;
        if (mat == 0)
            g_ckt[(((size_t)(l * NB + b) * NH + h) * DKH + dd) * ENCL + pnum] = acc[r];
        else
            g_cv[((size_t)(l * NB + b) * ENCL + pnum) * D + col] = acc[r];
    }
}

// ------------------------------------------------------------------ launch
extern "C" void kernel_launch(void* const* d_in, const int* in_sizes, int n_in,
                              void* d_out, int out_size) {
    Params p;
    const float* enc = (const float*)d_in[0];
    p.emb = (const float*)d_in[1];
    p.ln1 = (const float*)d_in[2];
    p.qw  = (const float*)d_in[3];
    p.kw  = (const float*)d_in[4];
    p.vw  = (const float*)d_in[5];
    p.ow  = (const float*)d_in[6];
    p.ln2 = (const float*)d_in[7];
    p.cqw = (const float*)d_in[8];
    const float* ckw = (const float*)d_in[9];
    const float* cvw = (const float*)d_in[10];
    p.cow = (const float*)d_in[11];
    p.ln3 = (const float*)d_in[12];
    p.wi  = (const float*)d_in[13];
    p.wo  = (const float*)d_in[14];
    p.fln = (const float*)d_in[15];
    p.rb  = (const float*)d_in[16];
    p.out = (float*)d_out;

    k_cross_kv<<<1536, 256>>>(enc, ckw, cvw);
    k_decode<<<NBLK, NTHR>>>(p);
}

// round 5
// speedup vs baseline: 1.1215x; 1.1215x over previous
#include <cuda_runtime.h>

#define D    768
#define NH   12
#define DKH  64
#define TT   16
#define ENCL 256
#define DFF  3072
#define NV   32128
#define NL   4
#define NB   2
#define EPSF 1e-6f
#define RSQRT_D 0.03608439182435161f   // 768^-0.5
#define NBLK 148
#define NTHR 512

// ------------------------------------------------------------------ scratch
__device__ float g_x  [NB*D];
__device__ float g_q  [NB*D];
__device__ float g_q2 [NB*D];
__device__ float g_att[NB*D];
__device__ float g_ff [NB*DFF];
__device__ float g_kc [NL*NB*TT*D];
__device__ float g_vc [NL*NB*TT*D];
__device__ float g_ckt[NL*NB*NH*DKH*ENCL];   // cross K transposed [l][b][h][dk][pos]
__device__ float g_cv [NL*NB*ENCL*D];        // cross V natural
__device__ unsigned long long g_bmax[2*NBLK];
__device__ unsigned g_flags[NBLK];

struct Params {
    const float *emb, *ln1, *qw, *kw, *vw, *ow, *ln2, *cqw, *cow, *ln3, *wi, *wo, *fln, *rb;
    float* out;
};

// ------------------------------------------------------------------ flag barrier (no atomic contention)
__device__ __forceinline__ void gsync(unsigned target) {
    __syncthreads();
    if (threadIdx.x == 0)
        asm volatile("st.release.gpu.global.u32 [%0], %1;"
                     :: "l"(g_flags + blockIdx.x), "r"(target) : "memory");
    if (threadIdx.x < 32) {
        bool ok;
        do {
            ok = true;
            #pragma unroll
            for (int i = 0; i < (NBLK + 31) / 32; i++) {
                int f = (int)threadIdx.x + i * 32;
                if (f < NBLK) {
                    unsigned v;
                    asm volatile("ld.acquire.gpu.global.u32 %0, [%1];"
                                 : "=r"(v) : "l"(g_flags + f) : "memory");
                    if ((int)(v - target) < 0) ok = false;
                }
            }
        } while (__any_sync(0xffffffffu, !ok));
        __threadfence();
    }
    __syncthreads();
}

// ------------------------------------------------------------------ rms (redundant per block), 512 thr
__device__ __forceinline__ float2 rms2(float* sred) {
    float s0 = 0.f, s1 = 0.f;
    for (int i = threadIdx.x; i < D; i += NTHR) {
        float a = __ldcg(&g_x[i]), b = __ldcg(&g_x[D + i]);
        s0 += a * a; s1 += b * b;
    }
    #pragma unroll
    for (int o = 16; o; o >>= 1) {
        s0 += __shfl_xor_sync(0xffffffffu, s0, o);
        s1 += __shfl_xor_sync(0xffffffffu, s1, o);
    }
    if ((threadIdx.x & 31) == 0) {
        sred[threadIdx.x >> 5]        = s0;
        sred[16 + (threadIdx.x >> 5)] = s1;
    }
    __syncthreads();
    if (threadIdx.x == 0) {
        float t0 = 0.f, t1 = 0.f;
        #pragma unroll
        for (int w = 0; w < 16; w++) { t0 += sred[w]; t1 += sred[16 + w]; }
        sred[32] = rsqrtf(t0 / (float)D + EPSF);
        sred[33] = rsqrtf(t1 / (float)D + EPSF);
    }
    __syncthreads();
    float2 r; r.x = sred[32]; r.y = sred[33];
    return r;
}

// ------------------------------------------------------------------ float4 GEMV slice
// block covers output cols [colpos*128, +128), rows [row0, row0 + 16*RPW)
// staged inputs sh0/sh1 are local-indexed from row0
template <int RPW>
__device__ __forceinline__ void gemv4(const float* __restrict__ W, int Dout,
    const float* sh0, const float* sh1, int colpos, int row0,
    float* red, float* o0, float* o1)
{
    int w = threadIdx.x >> 5, l = threadIdx.x & 31;
    int col = colpos * 128 + l * 4;
    const float* Wp = W + (size_t)(row0 + w * RPW) * Dout + col;
    float a00=0.f,a01=0.f,a02=0.f,a03=0.f,a10=0.f,a11=0.f,a12=0.f,a13=0.f;
    #pragma unroll
    for (int i = 0; i < RPW; i++) {
        float4 wv = *(const float4*)(Wp + (size_t)i * Dout);
        float x0 = sh0[w * RPW + i], x1 = sh1[w * RPW + i];
        a00 += x0 * wv.x; a01 += x0 * wv.y; a02 += x0 * wv.z; a03 += x0 * wv.w;
        a10 += x1 * wv.x; a11 += x1 * wv.y; a12 += x1 * wv.z; a13 += x1 * wv.w;
    }
    *(float4*)(red +        w * 128 + l * 4) = make_float4(a00, a01, a02, a03);
    *(float4*)(red + 2048 + w * 128 + l * 4) = make_float4(a10, a11, a12, a13);
    __syncthreads();
    if (threadIdx.x < 256) {
        int b = threadIdx.x >> 7, c = threadIdx.x & 127;
        const float* rb = red + b * 2048 + c;
        float sum = 0.f;
        #pragma unroll
        for (int ww = 0; ww < 16; ww++) sum += rb[ww * 128];
        atomicAdd((b ? o1 : o0) + colpos * 128 + c, sum);
    }
}

// ------------------------------------------------------------------ persistent decode kernel
__global__ __launch_bounds__(NTHR) void k_decode(Params p) {
    __shared__ float s[4608];           // red: s[0..4096), sh0: 4096, sh1: 4224, sred: 4352
    __shared__ unsigned long long sb[32];
    __shared__ int stok[NB];
    float* red  = s;
    float* sh0  = s + 4096;
    float* sh1  = s + 4224;
    float* sred = s + 4352;
    const int bx = blockIdx.x, tid = threadIdx.x;
    unsigned bar = g_flags[bx];

    // ---- init (each replay)
    for (int i = bx * NTHR + tid; i < NL * NB * TT * D; i += NBLK * NTHR) {
        g_kc[i] = 0.f; g_vc[i] = 0.f;
    }
    for (int i = bx * NTHR + tid; i < NB * D; i += NBLK * NTHR) { g_q[i] = 0.f; g_q2[i] = 0.f; }
    for (int i = bx * NTHR + tid; i < NB * DFF; i += NBLK * NTHR) g_ff[i] = 0.f;
    gsync(++bar);

    for (int t = 0; t < TT; t++) {
        // ================= embed (block 0 only; reduces per-block argmax)
        if (bx == 0) {
            if (t == 0) {
                if (tid < NB) stok[tid] = 0;
            } else if (tid < 64) {
                int b = tid >> 5, lane = tid & 31;
                unsigned long long m = 0ull;
                for (int i = lane; i < NBLK; i += 32) {
                    unsigned long long v = __ldcg(&g_bmax[b * NBLK + i]);
                    if (v > m) m = v;
                }
                #pragma unroll
                for (int o = 16; o; o >>= 1) {
                    unsigned long long v = __shfl_xor_sync(0xffffffffu, m, o);
                    if (v > m) m = v;
                }
                if (lane == 0) stok[b] = NV - 1 - (int)(m & 0xffffffffull);
            }
            __syncthreads();
            for (int i = tid; i < NB * D; i += NTHR) {
                int b = i / D, d = i % D;
                g_x[i] = p.emb[(size_t)stok[b] * D + d];
            }
        }
        gsync(++bar);

        for (int l = 0; l < NL; l++) {
            const size_t MO = (size_t)l * D * D;
            float* kcb = g_kc + ((size_t)(l * NB) * TT + t) * D;
            float* vcb = g_vc + ((size_t)(l * NB) * TT + t) * D;

            // ---- qkv: 144 blocks = mat(3) x colpos(6) x kblk(8), 96 rows/blk
            if (bx < 144) {
                float2 inv = rms2(sred);
                int mat = bx / 48, rem = bx % 48, colpos = rem >> 3, kblk = rem & 7;
                int row0 = kblk * 96;
                if (tid < 96) {
                    float wv = p.ln1[l * D + row0 + tid];
                    sh0[tid] = __ldcg(&g_x[row0 + tid])     * inv.x * wv;
                    sh1[tid] = __ldcg(&g_x[D + row0 + tid]) * inv.y * wv;
                }
                __syncthreads();
                if (mat == 0)      gemv4<6>(p.qw + MO, D, sh0, sh1, colpos, row0, red, g_q, g_q + D);
                else if (mat == 1) gemv4<6>(p.kw + MO, D, sh0, sh1, colpos, row0, red, kcb, kcb + TT * D);
                else               gemv4<6>(p.vw + MO, D, sh0, sh1, colpos, row0, red, vcb, vcb + TT * D);
            }
            gsync(++bar);

            // ---- self-attn (24 blocks) + idle zero g_q2, g_ff
            if (bx < 24) {
                int b = bx / NH, h = bx % NH;
                float* sq = s; float* sp = s + 64; float* se = s + 80;
                if (tid < DKH) sq[tid] = __ldcg(&g_q[b * D + h * DKH + tid]);
                __syncthreads();
                int n = t + 1;
                if (tid < n) {
                    const float* kp = g_kc + ((size_t)(l * NB + b) * TT + tid) * D + h * DKH;
                    float sc = 0.f;
                    #pragma unroll
                    for (int d = 0; d < DKH; d++) sc += sq[d] * __ldcg(kp + d);
                    sp[tid] = sc + p.rb[(t - tid) * NH + h];
                }
                __syncthreads();
                if (tid < n) {
                    float mx = -1e30f;
                    for (int j = 0; j < n; j++) mx = fmaxf(mx, sp[j]);
                    se[tid] = expf(sp[tid] - mx);
                }
                __syncthreads();
                if (tid < DKH) {
                    float sum = 0.f, o = 0.f;
                    for (int j = 0; j < n; j++) {
                        sum += se[j];
                        o += se[j] * __ldcg(&g_vc[((size_t)(l * NB + b) * TT + j) * D + h * DKH + tid]);
                    }
                    g_att[b * D + h * DKH + tid] = o / sum;
                }
            } else {
                int idx = (bx - 24) * NTHR + tid;
                if (idx < NB * D) g_q2[idx] = 0.f;
                else if (idx < NB * D + NB * DFF) g_ff[idx - NB * D] = 0.f;
            }
            gsync(++bar);

            // ---- o-proj + residual: colpos(6) x kblk(24), 32 rows/blk
            if (bx < 144) {
                int colpos = bx / 24, kblk = bx % 24, row0 = kblk * 32;
                if (tid < 32) {
                    sh0[tid] = __ldcg(&g_att[row0 + tid]);
                    sh1[tid] = __ldcg(&g_att[D + row0 + tid]);
                }
                __syncthreads();
                gemv4<2>(p.ow + MO, D, sh0, sh1, colpos, row0, red, g_x, g_x + D);
            }
            gsync(++bar);

            // ---- cq gemv into g_q2
            if (bx < 144) {
                float2 inv = rms2(sred);
                int colpos = bx / 24, kblk = bx % 24, row0 = kblk * 32;
                if (tid < 32) {
                    float wv = p.ln2[l * D + row0 + tid];
                    sh0[tid] = __ldcg(&g_x[row0 + tid])     * inv.x * wv;
                    sh1[tid] = __ldcg(&g_x[D + row0 + tid]) * inv.y * wv;
                }
                __syncthreads();
                gemv4<2>(p.cqw + MO, D, sh0, sh1, colpos, row0, red, g_q2, g_q2 + D);
            }
            gsync(++bar);

            // ---- cross-attn (24 blocks) + idle zero g_q
            if (bx < 24) {
                int b = bx / NH, h = bx % NH;
                float* sq  = s;        // 64
                float* se  = s + 64;   // 256
                float* rdw = s + 320;  // 8
                float* sMS = s + 328;  // 2
                float* so  = s + 336;  // 256
                if (tid < DKH) sq[tid] = __ldcg(&g_q2[b * D + h * DKH + tid]);
                __syncthreads();
                float sc = 0.f;
                if (tid < 256) {
                    const float* kt = g_ckt + ((size_t)((l * NB + b) * NH + h) * DKH) * ENCL;
                    #pragma unroll 16
                    for (int d = 0; d < DKH; d++) sc += sq[d] * kt[(size_t)d * ENCL + tid];
                    float m = sc;
                    #pragma unroll
                    for (int o = 16; o; o >>= 1) m = fmaxf(m, __shfl_xor_sync(0xffffffffu, m, o));
                    if ((tid & 31) == 0) rdw[tid >> 5] = m;
                }
                __syncthreads();
                if (tid == 0) {
                    float mm = rdw[0];
                    for (int w = 1; w < 8; w++) mm = fmaxf(mm, rdw[w]);
                    sMS[0] = mm;
                }
                __syncthreads();
                if (tid < 256) {
                    float e = expf(sc - sMS[0]);
                    se[tid] = e;
                    float ss = e;
                    #pragma unroll
                    for (int o = 16; o; o >>= 1) ss += __shfl_xor_sync(0xffffffffu, ss, o);
                    if ((tid & 31) == 0) rdw[tid >> 5] = ss;
                }
                __syncthreads();
                if (tid == 0) {
                    float t2 = 0.f;
                    for (int w = 0; w < 8; w++) t2 += rdw[w];
                    sMS[1] = t2;
                }
                __syncthreads();
                if (tid < 256) {
                    int g = tid >> 6, d = tid & 63;
                    const float* vp = g_cv + (size_t)((l * NB + b) * ENCL) * D + h * DKH + d;
                    float acc = 0.f;
                    for (int j = g * 64; j < g * 64 + 64; j++) acc += se[j] * vp[(size_t)j * D];
                    so[g * 64 + d] = acc;
                }
                __syncthreads();
                if (tid < DKH)
                    g_att[b * D + h * DKH + tid] =
                        (so[tid] + so[64 + tid] + so[128 + tid] + so[192 + tid]) / sMS[1];
            } else {
                int idx = (bx - 24) * NTHR + tid;
                if (idx < NB * D) g_q[idx] = 0.f;
            }
            gsync(++bar);

            // ---- co-proj + residual
            if (bx < 144) {
                int colpos = bx / 24, kblk = bx % 24, row0 = kblk * 32;
                if (tid < 32) {
                    sh0[tid] = __ldcg(&g_att[row0 + tid]);
                    sh1[tid] = __ldcg(&g_att[D + row0 + tid]);
                }
                __syncthreads();
                gemv4<2>(p.cow + MO, D, sh0, sh1, colpos, row0, red, g_x, g_x + D);
            }
            gsync(++bar);

            // ---- wi: colpos(24) x kblk(6), 128 rows/blk
            if (bx < 144) {
                float2 inv = rms2(sred);
                int colpos = bx / 6, kblk = bx % 6, row0 = kblk * 128;
                if (tid < 128) {
                    float wv = p.ln3[l * D + row0 + tid];
                    sh0[tid] = __ldcg(&g_x[row0 + tid])     * inv.x * wv;
                    sh1[tid] = __ldcg(&g_x[D + row0 + tid]) * inv.y * wv;
                }
                __syncthreads();
                gemv4<8>(p.wi + (size_t)l * D * DFF, DFF, sh0, sh1, colpos, row0, red,
                         g_ff, g_ff + DFF);
            }
            gsync(++bar);

            // ---- wo + residual: colpos(6) x kblk(24), 128 rows/blk
            if (bx < 144) {
                int colpos = bx / 24, kblk = bx % 24, row0 = kblk * 128;
                if (tid < 128) {
                    sh0[tid] = fmaxf(__ldcg(&g_ff[row0 + tid]), 0.f);
                    sh1[tid] = fmaxf(__ldcg(&g_ff[DFF + row0 + tid]), 0.f);
                }
                __syncthreads();
                gemv4<8>(p.wo + (size_t)l * DFF * D, D, sh0, sh1, colpos, row0, red,
                         g_x, g_x + D);
            }
            gsync(++bar);
        }

        // ================= final rms + logits + per-block argmax (all blocks)
        {
            float2 inv = rms2(sred);
            float* sx0 = s;          // 768
            float* sx1 = s + 1024;   // 768
            for (int i = tid; i < D; i += NTHR) {
                float w = p.fln[i] * RSQRT_D;
                sx0[i] = __ldcg(&g_x[i])     * inv.x * w;
                sx1[i] = __ldcg(&g_x[D + i]) * inv.y * w;
            }
            __syncthreads();
            int warp = tid >> 5, lane = tid & 31;
            unsigned long long best0 = 0ull, best1 = 0ull;
            for (int v = bx * 16 + warp; v < NV; v += NBLK * 16) {
                const float4* e = (const float4*)(p.emb + (size_t)v * D);
                float a0 = 0.f, a1 = 0.f;
                #pragma unroll
                for (int i = lane; i < D / 4; i += 32) {
                    float4 w = e[i];
                    a0 += w.x * sx0[4*i] + w.y * sx0[4*i+1] + w.z * sx0[4*i+2] + w.w * sx0[4*i+3];
                    a1 += w.x * sx1[4*i] + w.y * sx1[4*i+1] + w.z * sx1[4*i+2] + w.w * sx1[4*i+3];
                }
                #pragma unroll
                for (int o = 16; o; o >>= 1) {
                    a0 += __shfl_xor_sync(0xffffffffu, a0, o);
                    a1 += __shfl_xor_sync(0xffffffffu, a1, o);
                }
                if (lane == 0) {
                    p.out[((size_t)0 * TT + t) * NV + v] = a0;
                    p.out[((size_t)1 * TT + t) * NV + v] = a1;
                    unsigned b0 = __float_as_uint(a0);
                    unsigned b1 = __float_as_uint(a1);
                    unsigned u0 = (b0 & 0x80000000u) ? ~b0 : (b0 | 0x80000000u);
                    unsigned u1 = (b1 & 0x80000000u) ? ~b1 : (b1 | 0x80000000u);
                    unsigned long long k0 = ((unsigned long long)u0 << 32) | (unsigned)(NV - 1 - v);
                    unsigned long long k1 = ((unsigned long long)u1 << 32) | (unsigned)(NV - 1 - v);
                    if (k0 > best0) best0 = k0;
                    if (k1 > best1) best1 = k1;
                }
            }
            if (lane == 0) {
                sb[warp]      = best0;
                sb[16 + warp] = best1;
            }
            __syncthreads();
            if (tid < 2) {
                unsigned long long m = 0ull;
                #pragma unroll
                for (int w = 0; w < 16; w++) {
                    unsigned long long v = sb[tid * 16 + w];
                    if (v > m) m = v;
                }
                g_bmax[tid * NBLK + bx] = m;
            }
        }
        gsync(++bar);
    }
}

// ------------------------------------------------------------------ cross K/V precompute
__global__ __launch_bounds__(256) void k_cross_kv(
    const float* __restrict__ enc, const float* __restrict__ ckw,
    const float* __restrict__ cvw)
{
    __shared__ float sx[8][D];
    int bx = blockIdx.x;
    int c   = bx % 3; bx /= 3;
    int rb  = bx % 64; bx /= 64;
    int mat = bx % 2;
    int l   = bx / 2;
    int row0 = rb * 8;
    for (int i = threadIdx.x; i < 8 * D; i += 256)
        sx[i / D][i % D] = enc[(size_t)row0 * D + i];
    __syncthreads();
    const float* W = (mat == 0 ? ckw : cvw) + (size_t)l * D * D;
    int col = c * 256 + threadIdx.x;
    float acc[8];
    #pragma unroll
    for (int r = 0; r < 8; r++) acc[r] = 0.f;
    const float* Wp = W + col;
    #pragma unroll 4
    for (int i = 0; i < D; i++) {
        float w = Wp[(size_t)i * D];
        #pragma unroll
        for (int r = 0; r < 8; r++) acc[r] += sx[r][i] * w;
    }
    int h = col / DKH, dd = col % DKH;
    for (int r = 0; r < 8; r++) {
        int g = row0 + r; int b = g / ENCL; int pnum = g % ENCL;
        if (mat == 0)
            g_ckt[(((size_t)(l * NB + b) * NH + h) * DKH + dd) * ENCL + pnum] = acc[r];
        else
            g_cv[((size_t)(l * NB + b) * ENCL + pnum) * D + col] = acc[r];
    }
}

// ------------------------------------------------------------------ launch
extern "C" void kernel_launch(void* const* d_in, const int* in_sizes, int n_in,
                              void* d_out, int out_size) {
    Params p;
    const float* enc = (const float*)d_in[0];
    p.emb = (const float*)d_in[1];
    p.ln1 = (const float*)d_in[2];
    p.qw  = (const float*)d_in[3];
    p.kw  = (const float*)d_in[4];
    p.vw  = (const float*)d_in[5];
    p.ow  = (const float*)d_in[6];
    p.ln2 = (const float*)d_in[7];
    p.cqw = (const float*)d_in[8];
    const float* ckw = (const float*)d_in[9];
    const float* cvw = (const float*)d_in[10];
    p.cow = (const float*)d_in[11];
    p.ln3 = (const float*)d_in[12];
    p.wi  = (const float*)d_in[13];
    p.wo  = (const float*)d_in[14];
    p.fln = (const float*)d_in[15];
    p.rb  = (const float*)d_in[16];
    p.out = (float*)d_out;

    k_cross_kv<<<1536, 256>>>(enc, ckw, cvw);
    k_decode<<<NBLK, NTHR>>>(p);
}

// round 6
// speedup vs baseline: 1.6827x; 1.5004x over previous
#include <cuda_runtime.h>

#define D    768
#define NH   12
#define DKH  64
#define TT   16
#define ENCL 256
#define DFF  3072
#define NV   32128
#define NL   4
#define NB   2
#define EPSF 1e-6f
#define RSQRT_D 0.03608439182435161f   // 768^-0.5
#define NBLK 144
#define NTHR 512

// ------------------------------------------------------------------ scratch
__device__ float g_x  [NB*D];
__device__ float g_q  [NB*D];
__device__ float g_q2 [NB*D];
__device__ float g_att[NB*D];
__device__ float g_ff [NB*DFF];
__device__ float g_kc [NL*NB*TT*D];
__device__ float g_vc [NL*NB*TT*D];
__device__ float g_ckt[NL*NB*NH*DKH*ENCL];   // cross K transposed [l][b][h][dk][pos]
__device__ float g_cv [NL*NB*ENCL*D];        // cross V natural
__device__ unsigned long long g_bmax[2*NBLK];
__device__ unsigned g_flags[NBLK];

struct Params {
    const float *emb, *ln1, *qw, *kw, *vw, *ow, *ln2, *cqw, *cow, *ln3, *wi, *wo, *fln, *rb;
    float* out;
};

// ------------------------------------------------------------------ split barrier
__device__ __forceinline__ void g_arrive(unsigned target) {
    __syncthreads();
    if (threadIdx.x == 0)
        asm volatile("st.release.gpu.global.u32 [%0], %1;"
                     :: "l"(g_flags + blockIdx.x), "r"(target) : "memory");
}

__device__ __forceinline__ void g_waitbar(unsigned target) {
    if (threadIdx.x < 32) {
        bool ok;
        do {
            ok = true;
            #pragma unroll
            for (int i = 0; i < (NBLK + 31) / 32; i++) {
                int f = (int)threadIdx.x + i * 32;
                if (f < NBLK) {
                    unsigned v;
                    asm volatile("ld.acquire.gpu.global.u32 %0, [%1];"
                                 : "=r"(v) : "l"(g_flags + f) : "memory");
                    if ((int)(v - target) < 0) ok = false;
                }
            }
        } while (__any_sync(0xffffffffu, !ok));
        __threadfence();
    }
    __syncthreads();
}

// ------------------------------------------------------------------ cp.async weight prefetch
__device__ __forceinline__ void pf_tile(const float* __restrict__ W, int Dout,
                                        int row0, int colpos, int R, float* swbuf)
{
    const float* base = W + (size_t)row0 * Dout + (colpos << 7);
    unsigned sb_ = (unsigned)__cvta_generic_to_shared(swbuf);
    for (int chunk = threadIdx.x; chunk < R * 32; chunk += NTHR) {
        int r = chunk >> 5, c4 = (chunk & 31) << 2;
        asm volatile("cp.async.cg.shared.global [%0], [%1], 16;"
                     :: "r"(sb_ + (unsigned)(((r << 7) + c4) << 2)),
                        "l"(base + (size_t)r * Dout + c4) : "memory");
    }
    asm volatile("cp.async.commit_group;" ::: "memory");
}

// ------------------------------------------------------------------ rms over arbitrary rows
__device__ __forceinline__ float2 rms2p(const float* x0, const float* x1, float* sred) {
    float s0 = 0.f, s1 = 0.f;
    for (int i = threadIdx.x; i < D; i += NTHR) {
        float a = __ldcg(x0 + i), b = __ldcg(x1 + i);
        s0 += a * a; s1 += b * b;
    }
    #pragma unroll
    for (int o = 16; o; o >>= 1) {
        s0 += __shfl_xor_sync(0xffffffffu, s0, o);
        s1 += __shfl_xor_sync(0xffffffffu, s1, o);
    }
    if ((threadIdx.x & 31) == 0) {
        sred[threadIdx.x >> 5]        = s0;
        sred[16 + (threadIdx.x >> 5)] = s1;
    }
    __syncthreads();
    if (threadIdx.x == 0) {
        float t0 = 0.f, t1 = 0.f;
        #pragma unroll
        for (int w = 0; w < 16; w++) { t0 += sred[w]; t1 += sred[16 + w]; }
        sred[32] = rsqrtf(t0 / (float)D + EPSF);
        sred[33] = rsqrtf(t1 / (float)D + EPSF);
    }
    __syncthreads();
    float2 r; r.x = sred[32]; r.y = sred[33];
    return r;
}

// ------------------------------------------------------------------ smem-weight GEMV
// weights: sw row-major [R][128]; inputs sh0/sh1 [R]; outputs 128 cols x 2 batches
template <int R, int WG>
__device__ __forceinline__ void gemv_dyn(const float* sw,
    const float* sh0, const float* sh1, int colpos, float* part,
    float* o0, float* o1)
{
    if (WG) asm volatile("cp.async.wait_group 1;" ::: "memory");
    else    asm volatile("cp.async.wait_group 0;" ::: "memory");
    __syncthreads();
    const int tid = threadIdx.x;
    const int cg = tid & 31, bsel = (tid >> 5) & 1, slice = tid >> 6;
    const float* x = (bsel ? sh1 : sh0) + slice * (R / 8);
    const float4* w4 = (const float4*)sw + slice * (R / 8) * 32 + cg;
    float ax = 0.f, ay = 0.f, az = 0.f, aw = 0.f;
    #pragma unroll
    for (int r = 0; r < R / 8; r++) {
        float4 wv = w4[r * 32];
        float xv = x[r];
        ax += xv * wv.x; ay += xv * wv.y; az += xv * wv.z; aw += xv * wv.w;
    }
    ((float4*)part)[tid] = make_float4(ax, ay, az, aw);
    __syncthreads();
    if (tid < 256) {
        int cc = tid & 127, bs = tid >> 7;
        int g = cc >> 2, comp = cc & 3;
        float sum = 0.f;
        #pragma unroll
        for (int sl = 0; sl < 8; sl++)
            sum += part[((sl << 6) + (bs << 5) + g) * 4 + comp];
        atomicAdd((bs ? o1 : o0) + (colpos << 7) + cc, sum);
    }
}

// ------------------------------------------------------------------ persistent decode
__global__ __launch_bounds__(NTHR, 1) void k_decode(Params p) {
    extern __shared__ float dyn[];           // 2 x 16384 floats (2 x 64KB)
    float* buf0 = dyn;
    float* buf1 = dyn + 16384;
    __shared__ float s[2368];                // part[0..2048) sh0@2048 sh1@2176 sred@2304
    __shared__ unsigned long long sb[32];
    __shared__ int stok[NB];
    float* part = s;
    float* sh0  = s + 2048;
    float* sh1  = s + 2176;
    float* sred = s + 2304;
    const int bx = blockIdx.x, tid = threadIdx.x;
    unsigned bar = g_flags[bx];

    // ---- init (each replay)
    for (int i = bx * NTHR + tid; i < NL * NB * TT * D; i += NBLK * NTHR) {
        g_kc[i] = 0.f; g_vc[i] = 0.f;
    }
    for (int i = bx * NTHR + tid; i < NB * D; i += NBLK * NTHR) { g_q[i] = 0.f; g_q2[i] = 0.f; }
    for (int i = bx * NTHR + tid; i < NB * DFF; i += NBLK * NTHR) g_ff[i] = 0.f;

    // job decode shared across gemv phases
    const int mat    = bx / 48;                 // qkv only
    const int qrem   = bx % 48;
    const int qcol   = qrem >> 3,  qrow0 = (qrem & 7) * 96;   // qkv tiles
    const int scol   = bx / 24,    srow0 = (bx % 24) * 32;    // o/cq/co tiles
    const int wicol  = bx / 6,     wirow0 = (bx % 6) * 128;   // wi tiles
    const int worow0 = (bx % 24) * 128;                        // wo tiles (cols = scol)

    // prefetch qkv layer 0 into buf0
    {
        const float* W = (mat == 0 ? p.qw : (mat == 1 ? p.kw : p.vw));
        pf_tile(W, D, qrow0, qcol, 96, buf0);
    }
    g_arrive(++bar);

    for (int t = 0; t < TT; t++) {
        for (int l = 0; l < NL; l++) {
            const size_t MO = (size_t)l * D * D;
            float* kcb = g_kc + ((size_t)(l * NB) * TT + t) * D;
            float* vcb = g_vc + ((size_t)(l * NB) * TT + t) * D;

            // ============ P_qkv: compute (weights already in buf0)
            g_waitbar(bar);
            const float *x0, *x1;
            if (l == 0) {
                if (t == 0) {
                    if (tid < NB) stok[tid] = 0;
                } else if (tid < 64) {
                    int b = tid >> 5, lane = tid & 31;
                    unsigned long long m = 0ull;
                    for (int i = lane; i < NBLK; i += 32) {
                        unsigned long long v = __ldcg(&g_bmax[b * NBLK + i]);
                        if (v > m) m = v;
                    }
                    #pragma unroll
                    for (int o = 16; o; o >>= 1) {
                        unsigned long long v = __shfl_xor_sync(0xffffffffu, m, o);
                        if (v > m) m = v;
                    }
                    if (lane == 0) stok[b] = NV - 1 - (int)(m & 0xffffffffull);
                }
                __syncthreads();
                x0 = p.emb + (size_t)stok[0] * D;
                x1 = p.emb + (size_t)stok[1] * D;
                // 6 blocks materialize g_x = embeddings (for residual stream)
                if (mat == 0 && (qrem & 7) == 0 && tid < 256) {
                    int b = tid >> 7, cc = tid & 127;
                    g_x[b * D + qcol * 128 + cc] = __ldg(x0 + (b ? (x1 - x0) : 0) + qcol * 128 + cc);
                }
            } else {
                x0 = g_x; x1 = g_x + D;
            }
            {
                float2 inv = rms2p(x0, x1, sred);
                if (tid < 96) {
                    float wv = p.ln1[l * D + qrow0 + tid];
                    sh0[tid] = __ldcg(x0 + qrow0 + tid) * inv.x * wv;
                    sh1[tid] = __ldcg(x1 + qrow0 + tid) * inv.y * wv;
                }
                if (mat == 0)      gemv_dyn<96,0>(buf0, sh0, sh1, qcol, part, g_q, g_q + D);
                else if (mat == 1) gemv_dyn<96,0>(buf0, sh0, sh1, qcol, part, kcb, kcb + TT * D);
                else               gemv_dyn<96,0>(buf0, sh0, sh1, qcol, part, vcb, vcb + TT * D);
            }
            g_arrive(++bar);

            // ============ P_selfattn (+ pf o -> buf1)
            pf_tile(p.ow + MO, D, srow0, scol, 32, buf1);
            g_waitbar(bar);
            if (bx < 24) {
                int b = bx / NH, h = bx % NH;
                float* sq = s; float* sp = s + 64; float* se = s + 80;
                if (tid < DKH) sq[tid] = __ldcg(&g_q[b * D + h * DKH + tid]);
                __syncthreads();
                int n = t + 1;
                if (tid < n) {
                    const float* kp = g_kc + ((size_t)(l * NB + b) * TT + tid) * D + h * DKH;
                    float sc = 0.f;
                    #pragma unroll
                    for (int d = 0; d < DKH; d++) sc += sq[d] * __ldcg(kp + d);
                    sp[tid] = sc + p.rb[(t - tid) * NH + h];
                }
                __syncthreads();
                if (tid < n) {
                    float mx = -1e30f;
                    for (int j = 0; j < n; j++) mx = fmaxf(mx, sp[j]);
                    se[tid] = expf(sp[tid] - mx);
                }
                __syncthreads();
                if (tid < DKH) {
                    float sum = 0.f, o = 0.f;
                    for (int j = 0; j < n; j++) {
                        sum += se[j];
                        o += se[j] * __ldcg(&g_vc[((size_t)(l * NB + b) * TT + j) * D + h * DKH + tid]);
                    }
                    g_att[b * D + h * DKH + tid] = o / sum;
                }
            } else {
                int idx = (bx - 24) * NTHR + tid;
                if (idx < NB * D) g_q2[idx] = 0.f;
                else if (idx < NB * D + NB * DFF) g_ff[idx - NB * D] = 0.f;
            }
            g_arrive(++bar);

            // ============ P_o: compute from buf1 (+ pf cq -> buf0)
            pf_tile(p.cqw + MO, D, srow0, scol, 32, buf0);
            g_waitbar(bar);
            {
                if (tid < 32) {
                    sh0[tid] = __ldcg(&g_att[srow0 + tid]);
                    sh1[tid] = __ldcg(&g_att[D + srow0 + tid]);
                }
                gemv_dyn<32,1>(buf1, sh0, sh1, scol, part, g_x, g_x + D);
            }
            g_arrive(++bar);

            // ============ P_cq: compute from buf0
            g_waitbar(bar);
            {
                float2 inv = rms2p(g_x, g_x + D, sred);
                if (tid < 32) {
                    float wv = p.ln2[l * D + srow0 + tid];
                    sh0[tid] = __ldcg(&g_x[srow0 + tid])     * inv.x * wv;
                    sh1[tid] = __ldcg(&g_x[D + srow0 + tid]) * inv.y * wv;
                }
                gemv_dyn<32,0>(buf0, sh0, sh1, scol, part, g_q2, g_q2 + D);
            }
            g_arrive(++bar);

            // ============ P_xattn (+ pf co -> buf1)
            pf_tile(p.cow + MO, D, srow0, scol, 32, buf1);
            g_waitbar(bar);
            if (bx < 24) {
                int b = bx / NH, h = bx % NH;
                float* sq  = s;        // 64
                float* se  = s + 64;   // 256
                float* rdw = s + 320;  // 8
                float* sMS = s + 328;  // 2
                float* so  = s + 336;  // 256
                if (tid < DKH) sq[tid] = __ldcg(&g_q2[b * D + h * DKH + tid]);
                __syncthreads();
                float sc = 0.f;
                if (tid < 256) {
                    const float* kt = g_ckt + ((size_t)((l * NB + b) * NH + h) * DKH) * ENCL;
                    #pragma unroll 16
                    for (int d = 0; d < DKH; d++) sc += sq[d] * kt[(size_t)d * ENCL + tid];
                    float m = sc;
                    #pragma unroll
                    for (int o = 16; o; o >>= 1) m = fmaxf(m, __shfl_xor_sync(0xffffffffu, m, o));
                    if ((tid & 31) == 0) rdw[tid >> 5] = m;
                }
                __syncthreads();
                if (tid == 0) {
                    float mm = rdw[0];
                    for (int w = 1; w < 8; w++) mm = fmaxf(mm, rdw[w]);
                    sMS[0] = mm;
                }
                __syncthreads();
                if (tid < 256) {
                    float e = expf(sc - sMS[0]);
                    se[tid] = e;
                    float ss = e;
                    #pragma unroll
                    for (int o = 16; o; o >>= 1) ss += __shfl_xor_sync(0xffffffffu, ss, o);
                    if ((tid & 31) == 0) rdw[tid >> 5] = ss;
                }
                __syncthreads();
                if (tid == 0) {
                    float t2 = 0.f;
                    for (int w = 0; w < 8; w++) t2 += rdw[w];
                    sMS[1] = t2;
                }
                __syncthreads();
                if (tid < 256) {
                    int g = tid >> 6, d = tid & 63;
                    const float* vp = g_cv + (size_t)((l * NB + b) * ENCL) * D + h * DKH + d;
                    float acc = 0.f;
                    for (int j = g * 64; j < g * 64 + 64; j++) acc += se[j] * vp[(size_t)j * D];
                    so[g * 64 + d] = acc;
                }
                __syncthreads();
                if (tid < DKH)
                    g_att[b * D + h * DKH + tid] =
                        (so[tid] + so[64 + tid] + so[128 + tid] + so[192 + tid]) / sMS[1];
            } else {
                int idx = (bx - 24) * NTHR + tid;
                if (idx < NB * D) g_q[idx] = 0.f;
            }
            g_arrive(++bar);

            // ============ P_co: compute from buf1 (+ pf wi -> buf0)
            pf_tile(p.wi + (size_t)l * D * DFF, DFF, wirow0, wicol, 128, buf0);
            g_waitbar(bar);
            {
                if (tid < 32) {
                    sh0[tid] = __ldcg(&g_att[srow0 + tid]);
                    sh1[tid] = __ldcg(&g_att[D + srow0 + tid]);
                }
                gemv_dyn<32,1>(buf1, sh0, sh1, scol, part, g_x, g_x + D);
            }
            g_arrive(++bar);

            // ============ P_wi: compute from buf0 (+ pf wo -> buf1)
            pf_tile(p.wo + (size_t)l * DFF * D, D, worow0, scol, 128, buf1);
            g_waitbar(bar);
            {
                float2 inv = rms2p(g_x, g_x + D, sred);
                if (tid < 128) {
                    float wv = p.ln3[l * D + wirow0 + tid];
                    sh0[tid] = __ldcg(&g_x[wirow0 + tid])     * inv.x * wv;
                    sh1[tid] = __ldcg(&g_x[D + wirow0 + tid]) * inv.y * wv;
                }
                gemv_dyn<128,1>(buf0, sh0, sh1, wicol, part, g_ff, g_ff + DFF);
            }
            g_arrive(++bar);

            // ============ P_wo: compute from buf1 (+ pf next qkv -> buf0)
            {
                int nl = (l < NL - 1) ? l + 1 : 0;
                const float* W = (mat == 0 ? p.qw : (mat == 1 ? p.kw : p.vw)) + (size_t)nl * D * D;
                pf_tile(W, D, qrow0, qcol, 96, buf0);
            }
            g_waitbar(bar);
            {
                if (tid < 128) {
                    sh0[tid] = fmaxf(__ldcg(&g_ff[worow0 + tid]), 0.f);
                    sh1[tid] = fmaxf(__ldcg(&g_ff[DFF + worow0 + tid]), 0.f);
                }
                gemv_dyn<128,1>(buf1, sh0, sh1, scol, part, g_x, g_x + D);
            }
            g_arrive(++bar);
        }

        // ============ P_logits: final rms + logits + per-block argmax
        g_waitbar(bar);
        {
            float2 inv = rms2p(g_x, g_x + D, sred);
            float* sx0 = s;          // 768
            float* sx1 = s + 1024;   // 768
            for (int i = tid; i < D; i += NTHR) {
                float w = p.fln[i] * RSQRT_D;
                sx0[i] = __ldcg(&g_x[i])     * inv.x * w;
                sx1[i] = __ldcg(&g_x[D + i]) * inv.y * w;
            }
            __syncthreads();
            int warp = tid >> 5, lane = tid & 31;
            unsigned long long best0 = 0ull, best1 = 0ull;
            for (int v = bx * 16 + warp; v < NV; v += NBLK * 16) {
                const float4* e = (const float4*)(p.emb + (size_t)v * D);
                float a0 = 0.f, a1 = 0.f;
                #pragma unroll
                for (int i = lane; i < D / 4; i += 32) {
                    float4 w = e[i];
                    a0 += w.x * sx0[4*i] + w.y * sx0[4*i+1] + w.z * sx0[4*i+2] + w.w * sx0[4*i+3];
                    a1 += w.x * sx1[4*i] + w.y * sx1[4*i+1] + w.z * sx1[4*i+2] + w.w * sx1[4*i+3];
                }
                #pragma unroll
                for (int o = 16; o; o >>= 1) {
                    a0 += __shfl_xor_sync(0xffffffffu, a0, o);
                    a1 += __shfl_xor_sync(0xffffffffu, a1, o);
                }
                if (lane == 0) {
                    p.out[((size_t)0 * TT + t) * NV + v] = a0;
                    p.out[((size_t)1 * TT + t) * NV + v] = a1;
                    unsigned b0 = __float_as_uint(a0);
                    unsigned b1 = __float_as_uint(a1);
                    unsigned u0 = (b0 & 0x80000000u) ? ~b0 : (b0 | 0x80000000u);
                    unsigned u1 = (b1 & 0x80000000u) ? ~b1 : (b1 | 0x80000000u);
                    unsigned long long k0 = ((unsigned long long)u0 << 32) | (unsigned)(NV - 1 - v);
                    unsigned long long k1 = ((unsigned long long)u1 << 32) | (unsigned)(NV - 1 - v);
                    if (k0 > best0) best0 = k0;
                    if (k1 > best1) best1 = k1;
                }
            }
            if (lane == 0) { sb[warp] = best0; sb[16 + warp] = best1; }
            __syncthreads();
            if (tid < 2) {
                unsigned long long m = 0ull;
                #pragma unroll
                for (int w = 0; w < 16; w++) {
                    unsigned long long v = sb[tid * 16 + w];
                    if (v > m) m = v;
                }
                g_bmax[tid * NBLK + bx] = m;
            }
        }
        g_arrive(++bar);
    }
}

// ------------------------------------------------------------------ cross K/V precompute
__global__ __launch_bounds__(256) void k_cross_kv(
    const float* __restrict__ enc, const float* __restrict__ ckw,
    const float* __restrict__ cvw)
{
    __shared__ float sx[8][D];
    int bx = blockIdx.x;
    int c   = bx % 3; bx /= 3;
    int rb  = bx % 64; bx /= 64;
    int mat = bx % 2;
    int l   = bx / 2;
    int row0 = rb * 8;
    for (int i = threadIdx.x; i < 8 * D; i += 256)
        sx[i / D][i % D] = enc[(size_t)row0 * D + i];
    __syncthreads();
    const float* W = (mat == 0 ? ckw : cvw) + (size_t)l * D * D;
    int col = c * 256 + threadIdx.x;
    float acc[8];
    #pragma unroll
    for (int r = 0; r < 8; r++) acc[r] = 0.f;
    const float* Wp = W + col;
    #pragma unroll 4
    for (int i = 0; i < D; i++) {
        float w = Wp[(size_t)i * D];
        #pragma unroll
        for (int r = 0; r < 8; r++) acc[r] += sx[r][i] * w;
    }
    int h = col / DKH, dd = col % DKH;
    for (int r = 0; r < 8; r++) {
        int g = row0 + r; int b = g / ENCL; int pnum = g % ENCL;
        if (mat == 0)
            g_ckt[(((size_t)(l * NB + b) * NH + h) * DKH + dd) * ENCL + pnum] = acc[r];
        else
            g_cv[((size_t)(l * NB + b) * ENCL + pnum) * D + col] = acc[r];
    }
}

// ------------------------------------------------------------------ launch
extern "C" void kernel_launch(void* const* d_in, const int* in_sizes, int n_in,
                              void* d_out, int out_size) {
    Params p;
    const float* enc = (const float*)d_in[0];
    p.emb = (const float*)d_in[1];
    p.ln1 = (const float*)d_in[2];
    p.qw  = (const float*)d_in[3];
    p.kw  = (const float*)d_in[4];
    p.vw  = (const float*)d_in[5];
    p.ow  = (const float*)d_in[6];
    p.ln2 = (const float*)d_in[7];
    p.cqw = (const float*)d_in[8];
    const float* ckw = (const float*)d_in[9];
    const float* cvw = (const float*)d_in[10];
    p.cow = (const float*)d_in[11];
    p.ln3 = (const float*)d_in[12];
    p.wi  = (const float*)d_in[13];
    p.wo  = (const float*)d_in[14];
    p.fln = (const float*)d_in[15];
    p.rb  = (const float*)d_in[16];
    p.out = (float*)d_out;

    static int smem_set = 0;
    if (!smem_set) {
        cudaFuncSetAttribute(k_decode, cudaFuncAttributeMaxDynamicSharedMemorySize, 131072);
        smem_set = 1;
    }

    k_cross_kv<<<1536, 256>>>(enc, ckw, cvw);
    k_decode<<<NBLK, NTHR, 131072>>>(p);
}

// round 7
// speedup vs baseline: 2.5219x; 1.4987x over previous
#include <cuda_runtime.h>

#define D    768
#define NH   12
#define DKH  64
#define TT   16
#define ENCL 256
#define DFF  3072
#define NV   32128
#define NL   4
#define NB   2
#define EPSF 1e-6f
#define RSQRT_D 0.03608439182435161f   // 768^-0.5
#define NBLK 144
#define NTHR 512

// ------------------------------------------------------------------ scratch
__device__ float g_x  [NB*D];
__device__ float g_q  [NB*D];
__device__ float g_q2 [NB*D];
__device__ float g_ff [NB*DFF];
__device__ float g_kc [NL*NB*TT*D];
__device__ float g_vc [NL*NB*TT*D];
__device__ float g_ckt[NL*NB*NH*DKH*ENCL];   // cross K transposed [l][b][h][dk][pos]
__device__ float g_cv [NL*NB*ENCL*D];        // cross V natural
__device__ unsigned long long g_bmax[2*NBLK];
__device__ unsigned g_cnt;

struct Params {
    const float *emb, *ln1, *qw, *kw, *vw, *ow, *ln2, *cqw, *cow, *ln3, *wi, *wo, *fln, *rb;
    float* out;
};

// ------------------------------------------------------------------ counter barrier
__device__ __forceinline__ void g_arrive() {
    __syncthreads();
    if (threadIdx.x == 0)
        asm volatile("red.release.gpu.global.add.u32 [%0], 1;"
                     :: "l"(&g_cnt) : "memory");
}
__device__ __forceinline__ void g_waitbar(unsigned bar) {
    if (threadIdx.x == 0) {
        unsigned tgt = bar * NBLK, v;
        do {
            asm volatile("ld.acquire.gpu.global.u32 %0, [%1];"
                         : "=r"(v) : "l"(&g_cnt) : "memory");
        } while (v < tgt);
    }
    __syncthreads();
}

// ------------------------------------------------------------------ cp.async weight prefetch (evict_first)
__device__ __forceinline__ void pf_tile(const float* __restrict__ W, int Dout,
                                        int row0, int colpos, int R, float* swbuf,
                                        unsigned long long pol)
{
    const float* base = W + (size_t)row0 * Dout + (colpos << 7);
    unsigned sb_ = (unsigned)__cvta_generic_to_shared(swbuf);
    for (int chunk = threadIdx.x; chunk < R * 32; chunk += NTHR) {
        int r = chunk >> 5, c4 = (chunk & 31) << 2;
        asm volatile("cp.async.cg.shared.global.L2::cache_hint [%0], [%1], 16, %2;"
                     :: "r"(sb_ + (unsigned)(((r << 7) + c4) << 2)),
                        "l"(base + (size_t)r * Dout + c4), "l"(pol) : "memory");
    }
    asm volatile("cp.async.commit_group;" ::: "memory");
}

// ------------------------------------------------------------------ rms over arbitrary rows
__device__ __forceinline__ float2 rms2p(const float* x0, const float* x1, float* sred) {
    float s0 = 0.f, s1 = 0.f;
    for (int i = threadIdx.x; i < D; i += NTHR) {
        float a = __ldcg(x0 + i), b = __ldcg(x1 + i);
        s0 += a * a; s1 += b * b;
    }
    #pragma unroll
    for (int o = 16; o; o >>= 1) {
        s0 += __shfl_xor_sync(0xffffffffu, s0, o);
        s1 += __shfl_xor_sync(0xffffffffu, s1, o);
    }
    if ((threadIdx.x & 31) == 0) {
        sred[threadIdx.x >> 5]        = s0;
        sred[16 + (threadIdx.x >> 5)] = s1;
    }
    __syncthreads();
    if (threadIdx.x == 0) {
        float t0 = 0.f, t1 = 0.f;
        #pragma unroll
        for (int w = 0; w < 16; w++) { t0 += sred[w]; t1 += sred[16 + w]; }
        sred[32] = rsqrtf(t0 / (float)D + EPSF);
        sred[33] = rsqrtf(t1 / (float)D + EPSF);
    }
    __syncthreads();
    float2 r; r.x = sred[32]; r.y = sred[33];
    return r;
}

// ------------------------------------------------------------------ smem-weight GEMV (waits 1 pending group)
template <int R>
__device__ __forceinline__ void gemv_dyn(const float* sw,
    const float* sh0, const float* sh1, int colpos, float* part,
    float* o0, float* o1)
{
    asm volatile("cp.async.wait_group 1;" ::: "memory");
    __syncthreads();
    const int tid = threadIdx.x;
    const int cg = tid & 31, bsel = (tid >> 5) & 1, slice = tid >> 6;
    const float* x = (bsel ? sh1 : sh0) + slice * (R / 8);
    const float4* w4 = (const float4*)sw + slice * (R / 8) * 32 + cg;
    float ax = 0.f, ay = 0.f, az = 0.f, aw = 0.f;
    #pragma unroll
    for (int r = 0; r < R / 8; r++) {
        float4 wv = w4[r * 32];
        float xv = x[r];
        ax += xv * wv.x; ay += xv * wv.y; az += xv * wv.z; aw += xv * wv.w;
    }
    ((float4*)part)[tid] = make_float4(ax, ay, az, aw);
    __syncthreads();
    if (tid < 256) {
        int cc = tid & 127, bs = tid >> 7;
        int g = cc >> 2, comp = cc & 3;
        float sum = 0.f;
        #pragma unroll
        for (int sl = 0; sl < 8; sl++)
            sum += part[((sl << 6) + (bs << 5) + g) * 4 + comp];
        atomicAdd((bs ? o1 : o0) + (colpos << 7) + cc, sum);
    }
}

// ------------------------------------------------------------------ persistent decode
__global__ __launch_bounds__(NTHR, 1) void k_decode(Params p) {
    extern __shared__ float dyn[];           // 2 x 16384 floats
    float* buf0 = dyn;
    float* buf1 = dyn + 16384;
    __shared__ float s[2368];                // part s[0..2048) sh0@2048 sh1@2176 sred@2304
    __shared__ unsigned long long sb[32];
    __shared__ int stok[NB];
    float* part = s;
    float* sh0  = s + 2048;
    float* sh1  = s + 2176;
    float* sred = s + 2304;
    const int bx = blockIdx.x, tid = threadIdx.x;
    unsigned bar = 0;
    unsigned long long pol;
    asm volatile("createpolicy.fractional.L2::evict_first.b64 %0, 1.0;" : "=l"(pol));

    // ---- init (each replay)
    for (int i = bx * NTHR + tid; i < NL * NB * TT * D; i += NBLK * NTHR) {
        g_kc[i] = 0.f; g_vc[i] = 0.f;
    }
    for (int i = bx * NTHR + tid; i < NB * D; i += NBLK * NTHR) { g_q[i] = 0.f; g_q2[i] = 0.f; }
    for (int i = bx * NTHR + tid; i < NB * DFF; i += NBLK * NTHR) g_ff[i] = 0.f;

    // job decode
    const int mat    = bx / 48;
    const int qrem   = bx % 48;
    const int qcol   = qrem >> 3,  qrow0 = (qrem & 7) * 96;    // qkv tiles
    const int scol   = bx / 24,    srow0 = (bx % 24) * 32;     // o/cq/co tiles
    const int hh     = srow0 >> 6;                              // head for fused attn
    const int wicol  = bx / 6,     wirow0 = (bx % 6) * 128;    // wi tiles
    const int worow0 = (bx % 24) * 128;                        // wo tiles

    // prefetch qkv layer 0 into buf0 [group A]
    {
        const float* W = (mat == 0 ? p.qw : (mat == 1 ? p.kw : p.vw));
        pf_tile(W, D, qrow0, qcol, 96, buf0, pol);
    }
    g_arrive(); ++bar;

    for (int t = 0; t < TT; t++) {
        for (int l = 0; l < NL; l++) {
            const size_t MO = (size_t)l * D * D;
            float* kcb = g_kc + ((size_t)(l * NB) * TT + t) * D;
            float* vcb = g_vc + ((size_t)(l * NB) * TT + t) * D;

            // ============ P1 qkv (buf0); pf o -> buf1
            pf_tile(p.ow + MO, D, srow0, scol, 32, buf1, pol);
            g_waitbar(bar);
            const float *x0, *x1;
            if (l == 0) {
                if (t == 0) {
                    if (tid < NB) stok[tid] = 0;
                } else if (tid < 64) {
                    int b = tid >> 5, lane = tid & 31;
                    unsigned long long m = 0ull;
                    for (int i = lane; i < NBLK; i += 32) {
                        unsigned long long v = __ldcg(&g_bmax[b * NBLK + i]);
                        if (v > m) m = v;
                    }
                    #pragma unroll
                    for (int o = 16; o; o >>= 1) {
                        unsigned long long v = __shfl_xor_sync(0xffffffffu, m, o);
                        if (v > m) m = v;
                    }
                    if (lane == 0) stok[b] = NV - 1 - (int)(m & 0xffffffffull);
                }
                __syncthreads();
                x0 = p.emb + (size_t)stok[0] * D;
                x1 = p.emb + (size_t)stok[1] * D;
                if (mat == 0 && (qrem & 7) == 0 && tid < 256) {
                    int b = tid >> 7, cc = tid & 127;
                    g_x[b * D + qcol * 128 + cc] = __ldg((b ? x1 : x0) + qcol * 128 + cc);
                }
            } else {
                x0 = g_x; x1 = g_x + D;
            }
            if (bx < 12) g_ff[bx * 512 + tid] = 0.f;   // zero ff (consumed prev P6)
            {
                float2 inv = rms2p(x0, x1, sred);
                if (tid < 96) {
                    float wv = p.ln1[l * D + qrow0 + tid];
                    sh0[tid] = __ldcg(x0 + qrow0 + tid) * inv.x * wv;
                    sh1[tid] = __ldcg(x1 + qrow0 + tid) * inv.y * wv;
                }
                if (mat == 0)      gemv_dyn<96>(buf0, sh0, sh1, qcol, part, g_q, g_q + D);
                else if (mat == 1) gemv_dyn<96>(buf0, sh0, sh1, qcol, part, kcb, kcb + TT * D);
                else               gemv_dyn<96>(buf0, sh0, sh1, qcol, part, vcb, vcb + TT * D);
            }
            g_arrive(); ++bar;

            // ============ P2 self-attn (redundant, head hh) + o-proj (buf1); pf cq -> buf0
            pf_tile(p.cqw + MO, D, srow0, scol, 32, buf0, pol);
            g_waitbar(bar);
            {
                int n = t + 1;
                if (tid < 128) s[tid] = __ldcg(&g_q[(tid >> 6) * D + hh * DKH + (tid & 63)]);
                __syncthreads();
                if (tid < 32) {
                    int b = tid >> 4, j = tid & 15;
                    if (j < n) {
                        const float4* kp4 = (const float4*)(g_kc +
                            ((size_t)(l * NB + b) * TT + j) * D + hh * DKH);
                        float sc = 0.f;
                        #pragma unroll
                        for (int d4 = 0; d4 < 16; d4++) {
                            float4 kv = __ldg(kp4 + d4);
                            sc += s[b*64 + 4*d4]   * kv.x + s[b*64 + 4*d4+1] * kv.y
                                + s[b*64 + 4*d4+2] * kv.z + s[b*64 + 4*d4+3] * kv.w;
                        }
                        s[128 + b * 16 + j] = sc + p.rb[(t - j) * NH + hh];
                    }
                }
                __syncthreads();
                if (tid < 2) {
                    float mx = -1e30f;
                    for (int j = 0; j < n; j++) mx = fmaxf(mx, s[128 + tid * 16 + j]);
                    float sum = 0.f;
                    for (int j = 0; j < n; j++) {
                        float e = expf(s[128 + tid * 16 + j] - mx);
                        s[160 + tid * 16 + j] = e; sum += e;
                    }
                    s[192 + tid] = sum;
                }
                __syncthreads();
                if (tid < 64) {
                    int b = tid >> 5, c = tid & 31;
                    float acc = 0.f;
                    for (int j = 0; j < n; j++)
                        acc += s[160 + b * 16 + j] *
                               __ldg(&g_vc[((size_t)(l * NB + b) * TT + j) * D + srow0 + c]);
                    (b ? sh1 : sh0)[c] = acc / s[192 + b];
                }
                gemv_dyn<32>(buf1, sh0, sh1, scol, part, g_x, g_x + D);
            }
            g_arrive(); ++bar;

            // ============ P3 cq (buf0); pf co -> buf1; zero g_q
            pf_tile(p.cow + MO, D, srow0, scol, 32, buf1, pol);
            g_waitbar(bar);
            if (bx < 3) g_q[bx * 512 + tid] = 0.f;
            {
                float2 inv = rms2p(g_x, g_x + D, sred);
                if (tid < 32) {
                    float wv = p.ln2[l * D + srow0 + tid];
                    sh0[tid] = __ldcg(&g_x[srow0 + tid])     * inv.x * wv;
                    sh1[tid] = __ldcg(&g_x[D + srow0 + tid]) * inv.y * wv;
                }
                gemv_dyn<32>(buf0, sh0, sh1, scol, part, g_q2, g_q2 + D);
            }
            g_arrive(); ++bar;

            // ============ P4 cross-attn (redundant, head hh) + co-proj (buf1); pf wi -> buf0
            pf_tile(p.wi + (size_t)l * D * DFF, DFF, wirow0, wicol, 128, buf0, pol);
            g_waitbar(bar);
            {
                float* sq  = s;          // 128
                float* se  = s + 128;    // 512
                float* red = s + 640;    // 16
                float* sM  = s + 656;    // 2
                float* sS  = s + 658;    // 2
                float* pA  = s + 672;    // 512
                if (tid < 128) sq[tid] = __ldcg(&g_q2[(tid >> 6) * D + hh * DKH + (tid & 63)]);
                __syncthreads();
                int b = tid >> 8, pos = tid & 255;
                const float* kt = g_ckt + ((size_t)((l * NB + b) * NH + hh) * DKH) * ENCL;
                float sc = 0.f;
                #pragma unroll 16
                for (int d = 0; d < DKH; d++) sc += sq[b * 64 + d] * kt[(size_t)d * ENCL + pos];
                float m = sc;
                #pragma unroll
                for (int o = 16; o; o >>= 1) m = fmaxf(m, __shfl_xor_sync(0xffffffffu, m, o));
                if ((tid & 31) == 0) red[tid >> 5] = m;
                __syncthreads();
                if (tid < 2) {
                    float mm = red[tid * 8];
                    for (int w = 1; w < 8; w++) mm = fmaxf(mm, red[tid * 8 + w]);
                    sM[tid] = mm;
                }
                __syncthreads();
                float e = expf(sc - sM[b]);
                se[tid] = e;
                float ss = e;
                #pragma unroll
                for (int o = 16; o; o >>= 1) ss += __shfl_xor_sync(0xffffffffu, ss, o);
                if ((tid & 31) == 0) red[tid >> 5] = ss;
                __syncthreads();
                if (tid < 2) {
                    float tt = 0.f;
                    for (int w = 0; w < 8; w++) tt += red[tid * 8 + w];
                    sS[tid] = tt;
                }
                __syncthreads();
                {
                    int c = pos & 31, grp = pos >> 5;
                    const float* vp = g_cv + (size_t)((l * NB + b) * ENCL) * D + srow0 + c;
                    float acc = 0.f;
                    for (int j = grp * 32; j < grp * 32 + 32; j++)
                        acc += se[b * 256 + j] * vp[(size_t)j * D];
                    pA[b * 256 + grp * 32 + c] = acc;
                }
                __syncthreads();
                if (tid < 64) {
                    int bb = tid >> 5, c = tid & 31;
                    float sum = 0.f;
                    #pragma unroll
                    for (int g = 0; g < 8; g++) sum += pA[bb * 256 + g * 32 + c];
                    (bb ? sh1 : sh0)[c] = sum / sS[bb];
                }
                gemv_dyn<32>(buf1, sh0, sh1, scol, part, g_x, g_x + D);
            }
            g_arrive(); ++bar;

            // ============ P5 wi (buf0); pf wo -> buf1; zero g_q2
            pf_tile(p.wo + (size_t)l * DFF * D, D, worow0, scol, 128, buf1, pol);
            g_waitbar(bar);
            if (bx < 3) g_q2[bx * 512 + tid] = 0.f;
            {
                float2 inv = rms2p(g_x, g_x + D, sred);
                if (tid < 128) {
                    float wv = p.ln3[l * D + wirow0 + tid];
                    sh0[tid] = __ldcg(&g_x[wirow0 + tid])     * inv.x * wv;
                    sh1[tid] = __ldcg(&g_x[D + wirow0 + tid]) * inv.y * wv;
                }
                gemv_dyn<128>(buf0, sh0, sh1, wicol, part, g_ff, g_ff + DFF);
            }
            g_arrive(); ++bar;

            // ============ P6 wo (buf1); pf next qkv -> buf0
            {
                int nl = (l < NL - 1) ? l + 1 : 0;
                const float* W = (mat == 0 ? p.qw : (mat == 1 ? p.kw : p.vw)) + (size_t)nl * D * D;
                pf_tile(W, D, qrow0, qcol, 96, buf0, pol);
            }
            g_waitbar(bar);
            {
                if (tid < 128) {
                    sh0[tid] = fmaxf(__ldcg(&g_ff[worow0 + tid]), 0.f);
                    sh1[tid] = fmaxf(__ldcg(&g_ff[DFF + worow0 + tid]), 0.f);
                }
                gemv_dyn<128>(buf1, sh0, sh1, scol, part, g_x, g_x + D);
            }
            g_arrive(); ++bar;
        }

        // ============ PL logits + per-block argmax
        g_waitbar(bar);
        {
            float2 inv = rms2p(g_x, g_x + D, sred);
            float* sx0 = s;          // 768
            float* sx1 = s + 1024;   // 768
            for (int i = tid; i < D; i += NTHR) {
                float w = p.fln[i] * RSQRT_D;
                sx0[i] = __ldcg(&g_x[i])     * inv.x * w;
                sx1[i] = __ldcg(&g_x[D + i]) * inv.y * w;
            }
            __syncthreads();
            int warp = tid >> 5, lane = tid & 31;
            unsigned long long best0 = 0ull, best1 = 0ull;
            for (int v = bx * 16 + warp; v < NV; v += NBLK * 16) {
                const float4* e = (const float4*)(p.emb + (size_t)v * D);
                float a0 = 0.f, a1 = 0.f;
                #pragma unroll
                for (int i = lane; i < D / 4; i += 32) {
                    float4 w = e[i];
                    a0 += w.x * sx0[4*i] + w.y * sx0[4*i+1] + w.z * sx0[4*i+2] + w.w * sx0[4*i+3];
                    a1 += w.x * sx1[4*i] + w.y * sx1[4*i+1] + w.z * sx1[4*i+2] + w.w * sx1[4*i+3];
                }
                #pragma unroll
                for (int o = 16; o; o >>= 1) {
                    a0 += __shfl_xor_sync(0xffffffffu, a0, o);
                    a1 += __shfl_xor_sync(0xffffffffu, a1, o);
                }
                if (lane == 0) {
                    p.out[((size_t)0 * TT + t) * NV + v] = a0;
                    p.out[((size_t)1 * TT + t) * NV + v] = a1;
                    unsigned b0 = __float_as_uint(a0);
                    unsigned b1 = __float_as_uint(a1);
                    unsigned u0 = (b0 & 0x80000000u) ? ~b0 : (b0 | 0x80000000u);
                    unsigned u1 = (b1 & 0x80000000u) ? ~b1 : (b1 | 0x80000000u);
                    unsigned long long k0 = ((unsigned long long)u0 << 32) | (unsigned)(NV - 1 - v);
                    unsigned long long k1 = ((unsigned long long)u1 << 32) | (unsigned)(NV - 1 - v);
                    if (k0 > best0) best0 = k0;
                    if (k1 > best1) best1 = k1;
                }
            }
            if (lane == 0) { sb[warp] = best0; sb[16 + warp] = best1; }
            __syncthreads();
            if (tid < 2) {
                unsigned long long m = 0ull;
                #pragma unroll
                for (int w = 0; w < 16; w++) {
                    unsigned long long v = sb[tid * 16 + w];
                    if (v > m) m = v;
                }
                g_bmax[tid * NBLK + bx] = m;
            }
        }
        g_arrive(); ++bar;
    }
    asm volatile("cp.async.wait_group 0;" ::: "memory");
}

// ------------------------------------------------------------------ counter reset (per replay)
__global__ void k_reset() { g_cnt = 0; }

// ------------------------------------------------------------------ cross K/V precompute
__global__ __launch_bounds__(256) void k_cross_kv(
    const float* __restrict__ enc, const float* __restrict__ ckw,
    const float* __restrict__ cvw)
{
    __shared__ float sx[8][D];
    int bx = blockIdx.x;
    int c   = bx % 3; bx /= 3;
    int rb  = bx % 64; bx /= 64;
    int mat = bx % 2;
    int l   = bx / 2;
    int row0 = rb * 8;
    for (int i = threadIdx.x; i < 8 * D; i += 256)
        sx[i / D][i % D] = enc[(size_t)row0 * D + i];
    __syncthreads();
    const float* W = (mat == 0 ? ckw : cvw) + (size_t)l * D * D;
    int col = c * 256 + threadIdx.x;
    float acc[8];
    #pragma unroll
    for (int r = 0; r < 8; r++) acc[r] = 0.f;
    const float* Wp = W + col;
    #pragma unroll 4
    for (int i = 0; i < D; i++) {
        float w = Wp[(size_t)i * D];
        #pragma unroll
        for (int r = 0; r < 8; r++) acc[r] += sx[r][i] * w;
    }
    int h = col / DKH, dd = col % DKH;
    for (int r = 0; r < 8; r++) {
        int g = row0 + r; int b = g / ENCL; int pnum = g % ENCL;
        if (mat == 0)
            g_ckt[(((size_t)(l * NB + b) * NH + h) * DKH + dd) * ENCL + pnum] = acc[r];
        else
            g_cv[((size_t)(l * NB + b) * ENCL + pnum) * D + col] = acc[r];
    }
}

// ------------------------------------------------------------------ launch
extern "C" void kernel_launch(void* const* d_in, const int* in_sizes, int n_in,
                              void* d_out, int out_size) {
    Params p;
    const float* enc = (const float*)d_in[0];
    p.emb = (const float*)d_in[1];
    p.ln1 = (const float*)d_in[2];
    p.qw  = (const float*)d_in[3];
    p.kw  = (const float*)d_in[4];
    p.vw  = (const float*)d_in[5];
    p.ow  = (const float*)d_in[6];
    p.ln2 = (const float*)d_in[7];
    p.cqw = (const float*)d_in[8];
    const float* ckw = (const float*)d_in[9];
    const float* cvw = (const float*)d_in[10];
    p.cow = (const float*)d_in[11];
    p.ln3 = (const float*)d_in[12];
    p.wi  = (const float*)d_in[13];
    p.wo  = (const float*)d_in[14];
    p.fln = (const float*)d_in[15];
    p.rb  = (const float*)d_in[16];
    p.out = (float*)d_out;

    static int smem_set = 0;
    if (!smem_set) {
        cudaFuncSetAttribute(k_decode, cudaFuncAttributeMaxDynamicSharedMemorySize, 131072);
        smem_set = 1;
    }

    k_cross_kv<<<1536, 256>>>(enc, ckw, cvw);
    k_reset<<<1, 1>>>();
    k_decode<<<NBLK, NTHR, 131072>>>(p);
}